// round 5
// baseline (speedup 1.0000x reference)
#include <cuda_runtime.h>
#include <cstdint>

// Problem constants (fixed by the dataset)
#define NCH   12
#define GD    160
#define GH    160
#define GW    160
#define GVOL  (GD * GH * GW)          // 4,096,000 cells
#define NPTS  2097152

// Counting-sort buckets: voxel cell index >> 2 (groups of 4 x-adjacent cells)
#define NB    (GVOL / 4)              // 1,024,000 buckets
#define SBLK  1024
#define NSB   (NB / SBLK)             // 1000 scan blocks (exact)

__device__ int    g_counts[NB];       // 4.1 MB
__device__ int    g_offs[NB];         // 4.1 MB
__device__ int    g_bsums[NSB];
__device__ float4 g_sorted[NPTS];     // 32 MB: (x, y, z, bitcast(orig index))

// ---------------------------------------------------------------------------
// Shared coordinate -> cell mapping (must be identical in hist/scatter).
// Matches reference: u0 (pt x) -> D axis, u1 -> H, u2 -> W.
// ---------------------------------------------------------------------------
__device__ __forceinline__ int point_cell(
    float p0, float p1, float p2,
    float mn0, float mn1, float mn2,
    float mx0, float mx1, float mx2)
{
    float u0 = (p0 - mn0) / (mx0 - mn0);
    float u1 = (p1 - mn1) / (mx1 - mn1);
    float u2 = (p2 - mn2) / (mx2 - mn2);
    float px = u2 * (float)(GW - 1);
    float py = u1 * (float)(GH - 1);
    float pz = u0 * (float)(GD - 1);
    int x0 = min(max((int)floorf(px), 0), GW - 1);
    int y0 = min(max((int)floorf(py), 0), GH - 1);
    int z0 = min(max((int)floorf(pz), 0), GD - 1);
    return (z0 * GH + y0) * GW + x0;
}

// --------------------------- sort pipeline --------------------------------
__global__ void __launch_bounds__(256) zero_counts_kernel() {
    int i = blockIdx.x * blockDim.x + threadIdx.x;
    if (i < NB) g_counts[i] = 0;
}

__global__ void __launch_bounds__(256) hist_kernel(
    const float* __restrict__ xyz,
    const float* __restrict__ xyz_min,
    const float* __restrict__ xyz_max, int n)
{
    int i = blockIdx.x * blockDim.x + threadIdx.x;
    if (i >= n) return;
    float p0 = __ldcs(xyz + 3 * (size_t)i + 0);
    float p1 = __ldcs(xyz + 3 * (size_t)i + 1);
    float p2 = __ldcs(xyz + 3 * (size_t)i + 2);
    int b = point_cell(p0, p1, p2,
                       __ldg(xyz_min), __ldg(xyz_min + 1), __ldg(xyz_min + 2),
                       __ldg(xyz_max), __ldg(xyz_max + 1), __ldg(xyz_max + 2)) >> 2;
    atomicAdd(&g_counts[b], 1);   // no return use -> RED
}

__global__ void __launch_bounds__(SBLK) scan_block_kernel() {
    __shared__ int s[SBLK];
    int t = threadIdx.x;
    int i = blockIdx.x * SBLK + t;
    int v = g_counts[i];
    s[t] = v;
    __syncthreads();
#pragma unroll
    for (int off = 1; off < SBLK; off <<= 1) {
        int x = (t >= off) ? s[t - off] : 0;
        __syncthreads();
        s[t] += x;
        __syncthreads();
    }
    g_offs[i] = s[t] - v;                         // exclusive within block
    if (t == SBLK - 1) g_bsums[blockIdx.x] = s[t]; // block total
}

__global__ void __launch_bounds__(SBLK) scan_bsums_kernel() {
    __shared__ int s[SBLK];
    int t = threadIdx.x;
    int v = (t < NSB) ? g_bsums[t] : 0;
    s[t] = v;
    __syncthreads();
#pragma unroll
    for (int off = 1; off < SBLK; off <<= 1) {
        int x = (t >= off) ? s[t - off] : 0;
        __syncthreads();
        s[t] += x;
        __syncthreads();
    }
    if (t < NSB) g_bsums[t] = s[t] - v;           // exclusive block offsets
}

__global__ void __launch_bounds__(256) add_bsums_kernel() {
    int i = blockIdx.x * blockDim.x + threadIdx.x;
    if (i < NB) g_offs[i] += g_bsums[i >> 10];    // SBLK == 1024
}

__global__ void __launch_bounds__(256) scatter_kernel(
    const float* __restrict__ xyz,
    const float* __restrict__ xyz_min,
    const float* __restrict__ xyz_max, int n)
{
    int i = blockIdx.x * blockDim.x + threadIdx.x;
    if (i >= n) return;
    float p0 = __ldcs(xyz + 3 * (size_t)i + 0);
    float p1 = __ldcs(xyz + 3 * (size_t)i + 1);
    float p2 = __ldcs(xyz + 3 * (size_t)i + 2);
    int b = point_cell(p0, p1, p2,
                       __ldg(xyz_min), __ldg(xyz_min + 1), __ldg(xyz_min + 2),
                       __ldg(xyz_max), __ldg(xyz_max + 1), __ldg(xyz_max + 2)) >> 2;
    int pos = atomicAdd(&g_offs[b], 1);
    g_sorted[pos] = make_float4(p0, p1, p2, __int_as_float(i));
}

// ---------------------------------------------------------------------------
// Sample pass: points in spatially-sorted order -> warp-coherent gathers.
// Reads the ORIGINAL fp32 channel-first grid (exact precision, no convert).
// ---------------------------------------------------------------------------
__global__ void __launch_bounds__(256) trilinear_sample_sorted_kernel(
    const float* __restrict__ grid,
    const float* __restrict__ xyz_min,
    const float* __restrict__ xyz_max,
    float* __restrict__ out,
    int n)
{
    int j = blockIdx.x * blockDim.x + threadIdx.x;
    if (j >= n) return;

    float4 sp = __ldcs(&g_sorted[j]);
    float p0 = sp.x, p1 = sp.y, p2 = sp.z;
    int orig = __float_as_int(sp.w);

    float mn0 = __ldg(xyz_min + 0), mn1 = __ldg(xyz_min + 1), mn2 = __ldg(xyz_min + 2);
    float mx0 = __ldg(xyz_max + 0), mx1 = __ldg(xyz_max + 1), mx2 = __ldg(xyz_max + 2);

    float u0 = (p0 - mn0) / (mx0 - mn0);
    float u1 = (p1 - mn1) / (mx1 - mn1);
    float u2 = (p2 - mn2) / (mx2 - mn2);

    float px = u2 * (float)(GW - 1);
    float py = u1 * (float)(GH - 1);
    float pz = u0 * (float)(GD - 1);

    float xf = floorf(px), yf = floorf(py), zf = floorf(pz);
    float fx = px - xf,    fy = py - yf,    fz = pz - zf;

    int x0 = min(max((int)xf, 0), GW - 1);
    int y0 = min(max((int)yf, 0), GH - 1);
    int z0 = min(max((int)zf, 0), GD - 1);
    int x1 = min(x0 + 1, GW - 1);
    int y1 = min(y0 + 1, GH - 1);
    int z1 = min(z0 + 1, GD - 1);

    float wx0 = 1.0f - fx, wx1 = fx;
    float wy0 = 1.0f - fy, wy1 = fy;
    float wz0 = 1.0f - fz, wz1 = fz;

    float wp[4];
    wp[0] = wz0 * wy0;
    wp[1] = wz0 * wy1;
    wp[2] = wz1 * wy0;
    wp[3] = wz1 * wy1;

    int rowbase[4];
    rowbase[0] = (z0 * GH + y0) * GW;
    rowbase[1] = (z0 * GH + y1) * GW;
    rowbase[2] = (z1 * GH + y0) * GW;
    rowbase[3] = (z1 * GH + y1) * GW;

    float acc[NCH];
#pragma unroll
    for (int c = 0; c < NCH; c++) acc[c] = 0.0f;

#pragma unroll
    for (int p = 0; p < 4; p++) {
        const float* r0 = grid + rowbase[p] + x0;
        const float* r1 = grid + rowbase[p] + x1;
        float w0 = wp[p] * wx0;
        float w1 = wp[p] * wx1;
#pragma unroll
        for (int c = 0; c < NCH; c++) {
            float a = __ldg(r0 + (size_t)c * GVOL);
            float b = __ldg(r1 + (size_t)c * GVOL);
            acc[c] = fmaf(w0, a, fmaf(w1, b, acc[c]));
        }
    }

    // out is [N, 12] row-major; 48B per point, 16B-aligned -> 3x float4 stores
    float4* o = reinterpret_cast<float4*>(out + (size_t)orig * NCH);
    __stcs(o + 0, make_float4(acc[0], acc[1], acc[2],  acc[3]));
    __stcs(o + 1, make_float4(acc[4], acc[5], acc[6],  acc[7]));
    __stcs(o + 2, make_float4(acc[8], acc[9], acc[10], acc[11]));
}

extern "C" void kernel_launch(void* const* d_in, const int* in_sizes, int n_in,
                              void* d_out, int out_size) {
    const float* xyz     = (const float*)d_in[0];  // [N, 3]
    const float* grid    = (const float*)d_in[1];  // [1, 12, 160, 160, 160]
    const float* xyz_min = (const float*)d_in[2];  // [3]
    const float* xyz_max = (const float*)d_in[3];  // [3]
    float* out = (float*)d_out;                    // [N, 12]

    int n = in_sizes[0] / 3;
    int pt_blocks = (n + 255) / 256;

    zero_counts_kernel<<<(NB + 255) / 256, 256>>>();
    hist_kernel<<<pt_blocks, 256>>>(xyz, xyz_min, xyz_max, n);
    scan_block_kernel<<<NSB, SBLK>>>();
    scan_bsums_kernel<<<1, SBLK>>>();
    add_bsums_kernel<<<(NB + 255) / 256, 256>>>();
    scatter_kernel<<<pt_blocks, 256>>>(xyz, xyz_min, xyz_max, n);
    trilinear_sample_sorted_kernel<<<pt_blocks, 256>>>(grid, xyz_min, xyz_max, out, n);
}

// round 7
// speedup vs baseline: 1.1682x; 1.1682x over previous
#include <cuda_runtime.h>
#include <cuda_fp16.h>
#include <cstdint>

// Problem constants (fixed by the dataset)
#define NCH   12
#define GD    160
#define GH    160
#define GW    160
#define GVOL  (GD * GH * GW)          // 4,096,000 voxels

// Interleaved channel-last fp16 grid: [D*H*W, 12] = 24 B/voxel, 98.3 MB.
// +pad voxels so the unconditional (x0+1) read at the last voxel stays in
// bounds (its weight fx is exactly 0 there; padding is zero-initialized).
__device__ __align__(16) __half g_grid_h[((size_t)GVOL + 4) * NCH];

// ---- cache-policy load/store helpers (evict-last via createpolicy) --------
__device__ __forceinline__ uint64_t evict_last_policy() {
    uint64_t pol;
    asm("createpolicy.fractional.L2::evict_last.b64 %0, 1.0;" : "=l"(pol));
    return pol;
}
__device__ __forceinline__ uint2 ldg_el_u2(const void* p, uint64_t pol) {
    uint2 v;
    asm("ld.global.nc.L2::cache_hint.v2.u32 {%0,%1}, [%2], %3;"
        : "=r"(v.x), "=r"(v.y) : "l"(p), "l"(pol));
    return v;
}
__device__ __forceinline__ void stg_el_u4(void* p, uint4 v, uint64_t pol) {
    asm volatile("st.global.L2::cache_hint.v4.u32 [%0], {%1,%2,%3,%4}, %5;"
                 :: "l"(p), "r"(v.x), "r"(v.y), "r"(v.z), "r"(v.w), "l"(pol) : "memory");
}
__device__ __forceinline__ void stg_el_u2(void* p, uint2 v, uint64_t pol) {
    asm volatile("st.global.L2::cache_hint.v2.u32 [%0], {%1,%2}, %3;"
                 :: "l"(p), "r"(v.x), "r"(v.y), "l"(pol) : "memory");
}

// ---------------------------------------------------------------------------
// Pass 1: transpose+convert [C, D, H, W] fp32 -> [D*H*W, C] fp16.
// fp32 reads stream (evict-first); fp16 writes pinned toward L2 (evict-last)
// so the grid is L2-resident when the sample pass starts.
// ---------------------------------------------------------------------------
__global__ void __launch_bounds__(256) convert_cl_kernel(const float* __restrict__ grid) {
    int v = blockIdx.x * blockDim.x + threadIdx.x;
    if (v >= GVOL) return;

    uint64_t pol = evict_last_policy();

    __half h[NCH];
#pragma unroll
    for (int c = 0; c < NCH; c++)
        h[c] = __float2half(__ldcs(grid + (size_t)c * GVOL + v));

    char* dst = reinterpret_cast<char*>(g_grid_h) + (size_t)v * 24;
    // voxel base = v*24: 8B-aligned always; 16B-aligned for even v.
    if ((v & 1) == 0) {
        stg_el_u4(dst, *reinterpret_cast<const uint4*>(h), pol);
        stg_el_u2(dst + 16, *reinterpret_cast<const uint2*>(h + 8), pol);
    } else {
        const uint2* s = reinterpret_cast<const uint2*>(h);
        stg_el_u2(dst,      s[0], pol);
        stg_el_u2(dst + 8,  s[1], pol);
        stg_el_u2(dst + 16, s[2], pol);
    }
}

// ---------------------------------------------------------------------------
// Pass 2: trilinear sample, one thread per point, all 12 channels.
// All 24 gather loads (4 corner-pairs x 48 contiguous bytes) are issued
// before any FMA -> ~24 outstanding misses per warp. Occupancy traded for
// MLP via __launch_bounds__(256,3).
// ---------------------------------------------------------------------------
__device__ __forceinline__ float2 u2f2(unsigned u) {
    __half2 h = *reinterpret_cast<__half2*>(&u);
    return __half22float2(h);
}

__global__ void __launch_bounds__(256, 3) trilinear_sample_kernel(
    const float* __restrict__ xyz,
    const float* __restrict__ xyz_min,
    const float* __restrict__ xyz_max,
    float* __restrict__ out,
    int n)
{
    int i = blockIdx.x * blockDim.x + threadIdx.x;
    if (i >= n) return;

    float p0 = __ldcs(xyz + 3 * (size_t)i + 0);
    float p1 = __ldcs(xyz + 3 * (size_t)i + 1);
    float p2 = __ldcs(xyz + 3 * (size_t)i + 2);

    float mn0 = __ldg(xyz_min + 0), mn1 = __ldg(xyz_min + 1), mn2 = __ldg(xyz_min + 2);
    float mx0 = __ldg(xyz_max + 0), mx1 = __ldg(xyz_max + 1), mx2 = __ldg(xyz_max + 2);

    float u0 = (p0 - mn0) / (mx0 - mn0);
    float u1 = (p1 - mn1) / (mx1 - mn1);
    float u2 = (p2 - mn2) / (mx2 - mn2);

    // px indexes W (from u2), py indexes H (from u1), pz indexes D (from u0)
    float px = u2 * (float)(GW - 1);
    float py = u1 * (float)(GH - 1);
    float pz = u0 * (float)(GD - 1);

    float xf = floorf(px), yf = floorf(py), zf = floorf(pz);
    float fx = px - xf,    fy = py - yf,    fz = pz - zf;

    int x0 = min(max((int)xf, 0), GW - 1);
    int y0 = min(max((int)yf, 0), GH - 1);
    int z0 = min(max((int)zf, 0), GD - 1);
    int y1 = min(y0 + 1, GH - 1);
    int z1 = min(z0 + 1, GD - 1);

    float wx0 = 1.0f - fx, wx1 = fx;
    float wy0 = 1.0f - fy, wy1 = fy;
    float wz0 = 1.0f - fz, wz1 = fz;

    float wp[4];
    wp[0] = wz0 * wy0;
    wp[1] = wz0 * wy1;
    wp[2] = wz1 * wy0;
    wp[3] = wz1 * wy1;

    const char* gbase = reinterpret_cast<const char*>(g_grid_h);
    const char* vp[4];
    vp[0] = gbase + (size_t)((z0 * GH + y0) * GW + x0) * 24;
    vp[1] = gbase + (size_t)((z0 * GH + y1) * GW + x0) * 24;
    vp[2] = gbase + (size_t)((z1 * GH + y0) * GW + x0) * 24;
    vp[3] = gbase + (size_t)((z1 * GH + y1) * GW + x0) * 24;

    uint64_t pol = evict_last_policy();

    // Front-batch ALL gather loads: 4 pairs x 48 contiguous bytes = 24x LDG.64
    uint2 L[24];
#pragma unroll
    for (int p = 0; p < 4; p++) {
#pragma unroll
        for (int k = 0; k < 6; k++)
            L[p * 6 + k] = ldg_el_u2(vp[p] + 8 * k, pol);
    }

    float acc[NCH];
#pragma unroll
    for (int c = 0; c < NCH; c++) acc[c] = 0.0f;

#pragma unroll
    for (int p = 0; p < 4; p++) {
        float w0 = wp[p] * wx0;
        float w1 = wp[p] * wx1;
        const uint2* Px0 = &L[p * 6];      // ch0-11 of x0  (3x uint2)
        const uint2* Px1 = &L[p * 6 + 3];  // ch0-11 of x0+1

#pragma unroll
        for (int q = 0; q < 3; q++) {
            float2 a0 = u2f2(Px0[q].x), b0 = u2f2(Px1[q].x);
            float2 a1 = u2f2(Px0[q].y), b1 = u2f2(Px1[q].y);
            int c = q * 4;
            acc[c + 0] = fmaf(w0, a0.x, fmaf(w1, b0.x, acc[c + 0]));
            acc[c + 1] = fmaf(w0, a0.y, fmaf(w1, b0.y, acc[c + 1]));
            acc[c + 2] = fmaf(w0, a1.x, fmaf(w1, b1.x, acc[c + 2]));
            acc[c + 3] = fmaf(w0, a1.y, fmaf(w1, b1.y, acc[c + 3]));
        }
    }

    // out is [N, 12] row-major; 48B per thread -> 3x float4 streaming stores
    float4* o = reinterpret_cast<float4*>(out + (size_t)i * NCH);
    __stcs(o + 0, make_float4(acc[0], acc[1], acc[2],  acc[3]));
    __stcs(o + 1, make_float4(acc[4], acc[5], acc[6],  acc[7]));
    __stcs(o + 2, make_float4(acc[8], acc[9], acc[10], acc[11]));
}

extern "C" void kernel_launch(void* const* d_in, const int* in_sizes, int n_in,
                              void* d_out, int out_size) {
    const float* xyz     = (const float*)d_in[0];  // [N, 3]
    const float* grid    = (const float*)d_in[1];  // [1, 12, 160, 160, 160]
    const float* xyz_min = (const float*)d_in[2];  // [3]
    const float* xyz_max = (const float*)d_in[3];  // [3]
    float* out = (float*)d_out;                    // [N, 12]

    int n = in_sizes[0] / 3;

    {
        int threads = 256;
        int blocks = (GVOL + threads - 1) / threads;
        convert_cl_kernel<<<blocks, threads>>>(grid);
    }
    {
        int threads = 256;
        int blocks = (n + threads - 1) / threads;
        trilinear_sample_kernel<<<blocks, threads>>>(xyz, xyz_min, xyz_max, out, n);
    }
}